// round 9
// baseline (speedup 1.0000x reference)
#include <cuda_runtime.h>
#include <cstdint>

// ClusteringLayer: per-64-element-line greedy clustering, threshold 0.1f.
// Bases pairwise >= 0.1 apart => <=1 base per 0.1-wide bucket; matches confined
// to buckets k-1..k+1. Table entry packs {val (low 6 mantissa bits rounded
// away), appearance order (6 bits)} in one u32. Candidate eval uses ror6 so
// ord occupies the MSBs: one umin3 picks the earliest matching base.
// Empty = qNaN sentinel (match predicate always false).

#define THREADS   704           // 22 warps, 1 block/SM (smem-limited)
#define WARPS     22
#define THRESH    0.1f
#define SENTV     0x7FC00000u   // qNaN

// RN bucket magic: fb = RN(x*10 + 2^23 + 32); k = low mantissa bits in [1,62]
#define BMAGIC    8388640.0f    // 2^23 + 32
#define BLO       8388609.0f    // 2^23 + 1
#define BHI       8388670.0f    // 2^23 + 62

// per-warp smem (bytes):
//   [0,    8192)  vals: u32[64][32] packed {val|ord}   (bank==lane, CF)
//   [8192, 10240) stg : float4[32 lines][4 quads], quad XOR-swizzled
#define STG_OFF    8192
#define WARP_BYTES 10240
#define SMEM_TOTAL (WARP_BYTES * WARPS)     // 225280

extern __shared__ char smem_dyn[];

__global__ void __launch_bounds__(THREADS, 1)
cluster_kernel(const float* __restrict__ x, float* __restrict__ out, long n)
{
    const int tid  = threadIdx.x;
    const int wid  = tid >> 5;
    const int lane = tid & 31;

    char*     wbase = smem_dyn + (long)wid * WARP_BYTES;
    unsigned* vals  = (unsigned*)wbase;
    float4*   stg4  = (float4*)(wbase + STG_OFF);

    const uint4 sent4 = make_uint4(SENTV, SENTV, SENTV, SENTV);

    // init table to sentinel
    {
        uint4* vp = (uint4*)vals;
        #pragma unroll
        for (int j = 0; j < 16; j++) vp[j * 32 + lane] = sent4;
    }
    __syncwarp();

    const long n_lines = n >> 6;

    // tail copy (n % 64; zero for this shape, kept for generality)
    {
        const long tail0 = n_lines << 6;
        for (long t = (long)blockIdx.x * blockDim.x + tid + tail0; t < n;
             t += (long)gridDim.x * blockDim.x)
            out[t] = x[t];
    }

    const long n_batches = (n_lines + 31) >> 5;
    const long gwarp = (long)blockIdx.x * WARPS + wid;
    const long nwarp = (long)gridDim.x * WARPS;
    const int  lsw2  = (lane >> 1) & 3;          // staging swizzle for own line

    for (long b = gwarp; b < n_batches; b += nwarp) {
        const long line0 = b << 5;
        const float4* gin  = (const float4*)x   + (line0 << 4);
        float4*       gout = (float4*)out       + (line0 << 4);
        long nv_l = n_lines - line0;
        const int nvalid = (nv_l >= 32) ? 32 : (int)nv_l;
        const bool full = (nvalid == 32);

        #pragma unroll
        for (int h = 0; h < 4; h++) {            // 16-element quarters
            // ---- stage in: coalesced LDG.128, swizzled STS.128 (4-phase) ----
            #pragma unroll
            for (int c = 0; c < 4; c++) {
                const int idx = c * 32 + lane;   // 0..127
                const int l   = idx >> 2;
                const int q   = idx & 3;
                if (full || l < nvalid)
                    stg4[l * 4 + (q ^ ((l >> 1) & 3))] = gin[l * 16 + 4 * h + q];
            }
            __syncwarp();

            // ---- process 16 elements of own line, one quad at a time ----
            if (lane < nvalid) {
                #pragma unroll
                for (int qi = 0; qi < 4; qi++) {
                    const int sidx = lane * 4 + (qi ^ lsw2);
                    float4 xv = stg4[sidx];
                    float xin[4] = {xv.x, xv.y, xv.z, xv.w};
                    float o[4];
                    #pragma unroll
                    for (int j = 0; j < 4; j++) {
                        const float xi = xin[j];
                        const int   e  = 16 * h + 4 * qi + j;

                        float fb = fmaf(xi, 10.0f, BMAGIC);
                        fb = fminf(fmaxf(fb, BLO), BHI);
                        const int k  = __float_as_int(fb) & 63;   // 1..62
                        const int vi = k * 32 + lane;

                        const unsigned eL = vals[vi - 32];
                        const unsigned eC = vals[vi];
                        const unsigned eR = vals[vi + 32];

                        // ror6: ord -> MSBs; invalid -> all-ones (never a
                        // valid rot: all-ones entry is a NaN value, pred false)
                        const unsigned cL =
                            (fabsf(__uint_as_float(eL) - xi) < THRESH)
                                ? __funnelshift_r(eL, eL, 6) : 0xFFFFFFFFu;
                        const unsigned cC =
                            (fabsf(__uint_as_float(eC) - xi) < THRESH)
                                ? __funnelshift_r(eC, eC, 6) : 0xFFFFFFFFu;
                        const unsigned cR =
                            (fabsf(__uint_as_float(eR) - xi) < THRESH)
                                ? __funnelshift_r(eR, eR, 6) : 0xFFFFFFFFu;

                        const unsigned mk = min(min(cL, cC), cR);
                        const bool found = (mk != 0xFFFFFFFFu);

                        const unsigned win = __funnelshift_l(mk, mk, 6);
                        o[j] = found ? __uint_as_float(win) : xi;

                        const unsigned ne =
                            ((__float_as_uint(xi) + 32u) & ~63u) | (unsigned)e;
                        vals[vi] = found ? eC : ne;   // identity when found
                    }
                    stg4[sidx] = make_float4(o[0], o[1], o[2], o[3]);
                }
            }
            __syncwarp();

            // ---- stage out: swizzled LDS.128 (4-phase), coalesced STG.128 ----
            #pragma unroll
            for (int c = 0; c < 4; c++) {
                const int idx = c * 32 + lane;
                const int l   = idx >> 2;
                const int q   = idx & 3;
                if (full || l < nvalid)
                    gout[l * 16 + 4 * h + q] = stg4[l * 4 + (q ^ ((l >> 1) & 3))];
            }
            __syncwarp();
        }

        // ---- bulk cleanup: wipe table to sentinel (coalesced STS.128, CF) ----
        {
            uint4* vp = (uint4*)vals;
            #pragma unroll
            for (int j = 0; j < 16; j++) vp[j * 32 + lane] = sent4;
        }
        __syncwarp();
    }
}

extern "C" void kernel_launch(void* const* d_in, const int* in_sizes, int n_in,
                              void* d_out, int out_size)
{
    (void)n_in; (void)out_size;
    const float* x = (const float*)d_in[0];
    float* out = (float*)d_out;
    const long n = (long)in_sizes[0];

    cudaFuncSetAttribute(cluster_kernel,
                         cudaFuncAttributeMaxDynamicSharedMemorySize, SMEM_TOTAL);

    // 1 block/SM (smem-limited); grid-stride over 32-line warp batches.
    cluster_kernel<<<148, THREADS, SMEM_TOTAL>>>(x, out, n);
}

// round 10
// speedup vs baseline: 1.0112x; 1.0112x over previous
#include <cuda_runtime.h>
#include <cstdint>

// ClusteringLayer: per-64-element-line greedy clustering, threshold 0.1f.
// Bases pairwise >= 0.1 apart => <=1 base per 0.1-wide RN bucket; matches
// confined to buckets k-1..k+1. Table entry = {val rounded to 64 ulp, 6-bit
// appearance order} in one u32; candidate eval ror6 (ord->MSBs) + umin.
// QUAD-SPECULATIVE: all 12 probes for 4 elements issued on pre-quad state,
// then resolved in registers with cross-candidates (value test only).
// Empty = qNaN sentinel (match predicate false). Stores predicated.

#define THREADS   640           // 20 warps
#define WARPS     20
#define THRESH    0.1f
#define SENTV     0x7FC00000u   // qNaN

// RN bucket magic: fb = RN(x*10 + 2^23 + 32); k = low mantissa bits in [1,62]
#define BMAGIC    8388640.0f
#define BLO       8388609.0f
#define BHI       8388670.0f

// per-warp smem (bytes):
//   [0,    8192)  vals: u32[64][32] packed {val|ord}   (bank==lane, CF)
//   [8192, 10240) stg : float4[32 lines][4 quads], quad XOR-swizzled
#define STG_OFF    8192
#define WARP_BYTES 10240
#define SMEM_TOTAL (WARP_BYTES * WARPS)     // 204800

extern __shared__ char smem_dyn[];

__device__ __forceinline__ int bucket_idx(float xi) {
    float fb = fmaf(xi, 10.0f, BMAGIC);
    fb = fminf(fmaxf(fb, BLO), BHI);
    return __float_as_int(fb) & 63;          // 1..62
}
__device__ __forceinline__ unsigned cand(unsigned ev, float xi) {
    return (fabsf(__uint_as_float(ev) - xi) < THRESH)
               ? __funnelshift_r(ev, ev, 6) : 0xFFFFFFFFu;
}
__device__ __forceinline__ unsigned packv(float xi, int e) {
    return ((__float_as_uint(xi) + 32u) & ~63u) | (unsigned)e;
}

__global__ void __launch_bounds__(THREADS, 1)
cluster_kernel(const float* __restrict__ x, float* __restrict__ out, long n)
{
    const int tid  = threadIdx.x;
    const int wid  = tid >> 5;
    const int lane = tid & 31;

    char*     wbase = smem_dyn + (long)wid * WARP_BYTES;
    unsigned* vals  = (unsigned*)wbase;
    float4*   stg4  = (float4*)(wbase + STG_OFF);

    const uint4 sent4 = make_uint4(SENTV, SENTV, SENTV, SENTV);
    {
        uint4* vp = (uint4*)vals;
        #pragma unroll
        for (int j = 0; j < 16; j++) vp[j * 32 + lane] = sent4;
    }
    __syncwarp();

    const long n_lines = n >> 6;

    // tail copy (n % 64; zero for this shape, kept for generality)
    {
        const long tail0 = n_lines << 6;
        for (long t = (long)blockIdx.x * blockDim.x + tid + tail0; t < n;
             t += (long)gridDim.x * blockDim.x)
            out[t] = x[t];
    }

    const long n_batches = (n_lines + 31) >> 5;
    const long gwarp = (long)blockIdx.x * WARPS + wid;
    const long nwarp = (long)gridDim.x * WARPS;
    const int  lsw2  = (lane >> 1) & 3;

    for (long b = gwarp; b < n_batches; b += nwarp) {
        const long line0 = b << 5;
        const float4* gin  = (const float4*)x   + (line0 << 4);
        float4*       gout = (float4*)out       + (line0 << 4);
        long nv_l = n_lines - line0;
        const int nvalid = (nv_l >= 32) ? 32 : (int)nv_l;
        const bool full = (nvalid == 32);

        #pragma unroll
        for (int h = 0; h < 4; h++) {            // 16-element quarters
            // ---- stage in: coalesced LDG.128, swizzled STS.128 (CF) ----
            #pragma unroll
            for (int c = 0; c < 4; c++) {
                const int idx = c * 32 + lane;
                const int l   = idx >> 2;
                const int q   = idx & 3;
                if (full || l < nvalid)
                    stg4[l * 4 + (q ^ ((l >> 1) & 3))] = gin[l * 16 + 4 * h + q];
            }
            __syncwarp();

            // ---- process 16 elements: 4 quads, speculative within quad ----
            if (lane < nvalid) {
                #pragma unroll 1
                for (int qi = 0; qi < 4; qi++) {
                    const int sidx = lane * 8 * 0 + lane * 4 + (qi ^ lsw2);
                    float4 xv = stg4[sidx];
                    const float x0 = xv.x, x1 = xv.y, x2 = xv.z, x3 = xv.w;
                    const int e0 = 16 * h + 4 * qi;

                    const int vi0 = bucket_idx(x0) * 32 + lane;
                    const int vi1 = bucket_idx(x1) * 32 + lane;
                    const int vi2 = bucket_idx(x2) * 32 + lane;
                    const int vi3 = bucket_idx(x3) * 32 + lane;

                    // 12 probes on pre-quad state (latency overlapped)
                    const unsigned mk0 = min(min(cand(vals[vi0-32], x0),
                                                 cand(vals[vi0   ], x0)),
                                                 cand(vals[vi0+32], x0));
                    const unsigned mk1 = min(min(cand(vals[vi1-32], x1),
                                                 cand(vals[vi1   ], x1)),
                                                 cand(vals[vi1+32], x1));
                    const unsigned mk2 = min(min(cand(vals[vi2-32], x2),
                                                 cand(vals[vi2   ], x2)),
                                                 cand(vals[vi2+32], x2));
                    const unsigned mk3 = min(min(cand(vals[vi3-32], x3),
                                                 cand(vals[vi3   ], x3)),
                                                 cand(vals[vi3+32], x3));

                    // register-only resolve with cross-candidates
                    const bool f0 = (mk0 != 0xFFFFFFFFu);
                    const unsigned ne0 = packv(x0, e0);
                    const unsigned r0  = __funnelshift_r(ne0, ne0, 6);

                    const unsigned c01 = (!f0 && fabsf(x0 - x1) < THRESH)
                                             ? r0 : 0xFFFFFFFFu;
                    const unsigned m1  = min(mk1, c01);
                    const bool f1 = (m1 != 0xFFFFFFFFu);
                    const unsigned ne1 = packv(x1, e0 + 1);
                    const unsigned r1  = __funnelshift_r(ne1, ne1, 6);

                    const unsigned c02 = (!f0 && fabsf(x0 - x2) < THRESH)
                                             ? r0 : 0xFFFFFFFFu;
                    const unsigned c12 = (!f1 && fabsf(x1 - x2) < THRESH)
                                             ? r1 : 0xFFFFFFFFu;
                    const unsigned m2  = min(min(mk2, c02), c12);
                    const bool f2 = (m2 != 0xFFFFFFFFu);
                    const unsigned ne2 = packv(x2, e0 + 2);
                    const unsigned r2  = __funnelshift_r(ne2, ne2, 6);

                    const unsigned c03 = (!f0 && fabsf(x0 - x3) < THRESH)
                                             ? r0 : 0xFFFFFFFFu;
                    const unsigned c13 = (!f1 && fabsf(x1 - x3) < THRESH)
                                             ? r1 : 0xFFFFFFFFu;
                    const unsigned c23 = (!f2 && fabsf(x2 - x3) < THRESH)
                                             ? r2 : 0xFFFFFFFFu;
                    const unsigned m3  = min(min(min(mk3, c03), c13), c23);
                    const bool f3 = (m3 != 0xFFFFFFFFu);
                    const unsigned ne3 = packv(x3, e0 + 3);

                    // outputs (found -> packed winner incl. ord bits, as before)
                    float4 ov;
                    ov.x = f0 ? __uint_as_float(__funnelshift_l(mk0, mk0, 6)) : x0;
                    ov.y = f1 ? __uint_as_float(__funnelshift_l(m1,  m1,  6)) : x1;
                    ov.z = f2 ? __uint_as_float(__funnelshift_l(m2,  m2,  6)) : x2;
                    ov.w = f3 ? __uint_as_float(__funnelshift_l(m3,  m3,  6)) : x3;
                    stg4[sidx] = ov;

                    // predicated inserts (distinct buckets guaranteed)
                    if (!f0) vals[vi0] = ne0;
                    if (!f1) vals[vi1] = ne1;
                    if (!f2) vals[vi2] = ne2;
                    if (!f3) vals[vi3] = ne3;
                }
            }
            __syncwarp();

            // ---- stage out: swizzled LDS.128 (CF), coalesced STG.128 ----
            #pragma unroll
            for (int c = 0; c < 4; c++) {
                const int idx = c * 32 + lane;
                const int l   = idx >> 2;
                const int q   = idx & 3;
                if (full || l < nvalid)
                    gout[l * 16 + 4 * h + q] = stg4[l * 4 + (q ^ ((l >> 1) & 3))];
            }
            __syncwarp();
        }

        // ---- bulk cleanup: wipe table to sentinel (coalesced STS.128) ----
        {
            uint4* vp = (uint4*)vals;
            #pragma unroll
            for (int j = 0; j < 16; j++) vp[j * 32 + lane] = sent4;
        }
        __syncwarp();
    }
}

extern "C" void kernel_launch(void* const* d_in, const int* in_sizes, int n_in,
                              void* d_out, int out_size)
{
    (void)n_in; (void)out_size;
    const float* x = (const float*)d_in[0];
    float* out = (float*)d_out;
    const long n = (long)in_sizes[0];

    cudaFuncSetAttribute(cluster_kernel,
                         cudaFuncAttributeMaxDynamicSharedMemorySize, SMEM_TOTAL);

    cluster_kernel<<<148, THREADS, SMEM_TOTAL>>>(x, out, n);
}